// round 1
// baseline (speedup 1.0000x reference)
#include <cuda_runtime.h>
#include <cuda_bf16.h>
#include <math.h>

// Problem constants
#define Bb   2
#define NN_  2048
#define CC   1024
#define HH   16
#define DD   64
#define DFF_ 4096

// Scratch buffers (static device globals — allocation-free rule)
__device__ float g_ln[Bb * NN_ * CC];          // 16 MB  (xn for ln1, reused for ln2)
__device__ float g_qkv[Bb * NN_ * 3 * CC];     // 50 MB
__device__ float g_attnout[Bb * NN_ * CC];     // 16 MB  (attn @ V, re-packed [B,N,C])
__device__ float g_x1[Bb * NN_ * CC];          // 16 MB  (x + attn_proj)
__device__ float g_hbuf[Bb * NN_ * DFF_];      // 67 MB  (gelu(fc1))

// ---------------------------------------------------------------------------
// LayerNorm: one block (256 threads) per row of C=1024
// ---------------------------------------------------------------------------
__global__ void ln_kernel(const float* __restrict__ x,
                          const float* __restrict__ g,
                          const float* __restrict__ b,
                          float* __restrict__ out)
{
    int row = blockIdx.x;
    long long base = (long long)row * CC;
    int t = threadIdx.x;

    float v[4];
    float s = 0.f, s2 = 0.f;
#pragma unroll
    for (int i = 0; i < 4; i++) {
        v[i] = x[base + t + i * 256];
        s  += v[i];
        s2 += v[i] * v[i];
    }
    // warp reduce
#pragma unroll
    for (int o = 16; o; o >>= 1) {
        s  += __shfl_xor_sync(0xffffffffu, s, o);
        s2 += __shfl_xor_sync(0xffffffffu, s2, o);
    }
    __shared__ float sh[16];
    int w = t >> 5, l = t & 31;
    if (l == 0) { sh[w] = s; sh[8 + w] = s2; }
    __syncthreads();
    if (t == 0) {
        float a = 0.f, c = 0.f;
#pragma unroll
        for (int i = 0; i < 8; i++) { a += sh[i]; c += sh[8 + i]; }
        sh[0] = a; sh[8] = c;
    }
    __syncthreads();
    float mu  = sh[0] * (1.0f / CC);
    float var = sh[8] * (1.0f / CC) - mu * mu;
    float inv = rsqrtf(var + 1e-5f);
#pragma unroll
    for (int i = 0; i < 4; i++) {
        int c = t + i * 256;
        out[base + c] = (v[i] - mu) * inv * g[c] + b[c];
    }
}

// ---------------------------------------------------------------------------
// Generic tiled SGEMM: C = A @ op(B)  (+bias, +gelu, +residual)
//   BT=true : B is [Nc, K] row-major (NT gemm, dot of rows) — torch Linear weight
//   BT=false: B is [K, Nc] row-major (NN gemm)
// Block tile 64x64, K tile 16, 256 threads, 4x4 per thread.
// blockIdx.z = batch*head index; offsets = b*{A,B,C}bs + h*{A,B,C}hs.
// All dims must be multiples of the tile sizes (they are for this problem).
// ---------------------------------------------------------------------------
__device__ __forceinline__ float gelu_exact(float v) {
    return 0.5f * v * (1.0f + erff(v * 0.70710678118654752f));
}

template <bool BT>
__global__ void gemm64(const float* __restrict__ A, const float* __restrict__ Bm,
                       float* __restrict__ Cc,
                       int M, int Nc, int K, int lda, int ldb, int ldc,
                       long long Abs, long long Ahs,
                       long long Bbs, long long Bhs,
                       long long Cbs, long long Chs, int Hh,
                       const float* __restrict__ bias,
                       const float* __restrict__ res, int act)
{
    const int BK = 16;
    int zb = blockIdx.z / Hh, zh = blockIdx.z % Hh;
    A  += zb * Abs + zh * Ahs;
    Bm += zb * Bbs + zh * Bhs;
    Cc += zb * Cbs + zh * Chs;

    __shared__ float As[BK][64];
    __shared__ float Bs[BK][64 + 4];

    int t  = threadIdx.x;            // 0..255
    int m0 = blockIdx.y * 64;
    int n0 = blockIdx.x * 64;
    int tx = t & 15, ty = t >> 4;

    int arow = t >> 2;               // 0..63
    int akk  = (t & 3) * 4;          // 0,4,8,12

    float acc[4][4] = {};

    for (int k0 = 0; k0 < K; k0 += BK) {
        float4 av = *reinterpret_cast<const float4*>(
            &A[(long long)(m0 + arow) * lda + k0 + akk]);
        As[akk + 0][arow] = av.x;
        As[akk + 1][arow] = av.y;
        As[akk + 2][arow] = av.z;
        As[akk + 3][arow] = av.w;

        if (BT) {
            float4 bv = *reinterpret_cast<const float4*>(
                &Bm[(long long)(n0 + arow) * ldb + k0 + akk]);
            Bs[akk + 0][arow] = bv.x;
            Bs[akk + 1][arow] = bv.y;
            Bs[akk + 2][arow] = bv.z;
            Bs[akk + 3][arow] = bv.w;
        } else {
            int krow = t >> 4;       // 0..15
            int ncol = (t & 15) * 4; // 0..60
            float4 bv = *reinterpret_cast<const float4*>(
                &Bm[(long long)(k0 + krow) * ldb + n0 + ncol]);
            *reinterpret_cast<float4*>(&Bs[krow][ncol]) = bv;
        }
        __syncthreads();

#pragma unroll
        for (int kk = 0; kk < BK; kk++) {
            float4 a4 = *reinterpret_cast<const float4*>(&As[kk][ty * 4]);
            float4 b4 = *reinterpret_cast<const float4*>(&Bs[kk][tx * 4]);
            float ar[4] = {a4.x, a4.y, a4.z, a4.w};
            float br[4] = {b4.x, b4.y, b4.z, b4.w};
#pragma unroll
            for (int i = 0; i < 4; i++)
#pragma unroll
                for (int j = 0; j < 4; j++)
                    acc[i][j] += ar[i] * br[j];
        }
        __syncthreads();
    }

#pragma unroll
    for (int i = 0; i < 4; i++) {
        int mm = m0 + ty * 4 + i;
#pragma unroll
        for (int j = 0; j < 4; j++) {
            int nn = n0 + tx * 4 + j;
            float v = acc[i][j];
            if (bias) v += bias[nn];
            if (act)  v = gelu_exact(v);
            long long idx = (long long)mm * ldc + nn;
            if (res) v += res[idx];
            Cc[idx] = v;
        }
    }
}

// ---------------------------------------------------------------------------
// Softmax (in place on attn logits): applies scale + mask, row length N=2048.
// One block (256 threads) per row; rows = B*H*N = 65536.
// ---------------------------------------------------------------------------
__global__ void softmax_kernel(float* __restrict__ attn,
                               const int* __restrict__ mask)
{
    long long row = blockIdx.x;
    int bidx = (int)(row / ((long long)HH * NN_));
    float* r = attn + row * NN_;
    const int* mr = mask + (long long)bidx * NN_;
    int t = threadIdx.x;

    const float scale = 0.125f; // D^-0.5, D=64

    float v[8];
    float mx = -INFINITY;
#pragma unroll
    for (int i = 0; i < 8; i++) {
        int c = t + i * 256;
        float val = mr[c] ? r[c] * scale : -INFINITY;
        v[i] = val;
        mx = fmaxf(mx, val);
    }
#pragma unroll
    for (int o = 16; o; o >>= 1)
        mx = fmaxf(mx, __shfl_xor_sync(0xffffffffu, mx, o));

    __shared__ float shm[8], shs[8];
    int w = t >> 5, l = t & 31;
    if (l == 0) shm[w] = mx;
    __syncthreads();
    float m2 = shm[0];
#pragma unroll
    for (int i = 1; i < 8; i++) m2 = fmaxf(m2, shm[i]);

    float se = 0.f;
#pragma unroll
    for (int i = 0; i < 8; i++) {
        v[i] = expf(v[i] - m2);   // exp(-inf - finite) = 0 for masked cols
        se += v[i];
    }
#pragma unroll
    for (int o = 16; o; o >>= 1)
        se += __shfl_xor_sync(0xffffffffu, se, o);
    if (l == 0) shs[w] = se;
    __syncthreads();
    float tot = 0.f;
#pragma unroll
    for (int i = 0; i < 8; i++) tot += shs[i];
    float inv = 1.0f / tot;

#pragma unroll
    for (int i = 0; i < 8; i++) {
        int c = t + i * 256;
        r[c] = v[i] * inv;
    }
}

// ---------------------------------------------------------------------------
// Launch
// ---------------------------------------------------------------------------
extern "C" void kernel_launch(void* const* d_in, const int* in_sizes, int n_in,
                              void* d_out, int out_size)
{
    const float* x      = (const float*)d_in[0];
    const int*   mask   = (const int*)  d_in[1];
    const float* qkv_w  = (const float*)d_in[2];
    const float* proj_w = (const float*)d_in[3];
    const float* proj_b = (const float*)d_in[4];
    const float* ln1_g  = (const float*)d_in[5];
    const float* ln1_b  = (const float*)d_in[6];
    const float* ln2_g  = (const float*)d_in[7];
    const float* ln2_b  = (const float*)d_in[8];
    const float* fc1_w  = (const float*)d_in[9];
    const float* fc1_b  = (const float*)d_in[10];
    const float* fc2_w  = (const float*)d_in[11];
    const float* fc2_b  = (const float*)d_in[12];

    float* out_x    = (float*)d_out;                               // [B,N,C]
    float* out_attn = out_x + (long long)Bb * NN_ * CC;            // [B,H,N,N]

    float *p_ln, *p_qkv, *p_ao, *p_x1, *p_h;
    cudaGetSymbolAddress((void**)&p_ln,  g_ln);
    cudaGetSymbolAddress((void**)&p_qkv, g_qkv);
    cudaGetSymbolAddress((void**)&p_ao,  g_attnout);
    cudaGetSymbolAddress((void**)&p_x1,  g_x1);
    cudaGetSymbolAddress((void**)&p_h,   g_hbuf);

    const int M  = Bb * NN_;            // 4096 flattened rows
    const long long ZERO = 0;

    // 1) LN1: g_ln = layernorm(x)
    ln_kernel<<<M, 256>>>(x, ln1_g, ln1_b, p_ln);

    // 2) QKV: g_qkv[4096,3072] = g_ln[4096,1024] @ qkv_w^T
    {
        dim3 grid(3 * CC / 64, M / 64, 1);
        gemm64<true><<<grid, 256>>>(p_ln, qkv_w, p_qkv,
                                    M, 3 * CC, CC, CC, CC, 3 * CC,
                                    ZERO, ZERO, ZERO, ZERO, ZERO, ZERO, 1,
                                    nullptr, nullptr, 0);
    }

    // 3) QK^T per head: logits -> out_attn (raw, un-scaled)
    //    Q[b,h][n,k] = qkv[b*3NC + n*3C + h*D + k]      (lda = 3C)
    //    K slice: same +C offset.
    {
        const long long NC3 = (long long)NN_ * 3 * CC;
        dim3 grid(NN_ / 64, NN_ / 64, Bb * HH);
        gemm64<true><<<grid, 256>>>(p_qkv, p_qkv + CC, out_attn,
                                    NN_, NN_, DD, 3 * CC, 3 * CC, NN_,
                                    NC3, DD, NC3, DD,
                                    (long long)HH * NN_ * NN_, (long long)NN_ * NN_, HH,
                                    nullptr, nullptr, 0);
    }

    // 4) softmax (scale + mask fused), in place in out_attn
    softmax_kernel<<<Bb * HH * NN_, 256>>>(out_attn, mask);

    // 5) AV per head: g_attnout[b,n, h*D+d] = attn[b,h] @ V[b,h]
    //    V[b,h][m,d] = qkv[b*3NC + m*3C + 2C + h*D + d]  (B non-transposed, ldb = 3C)
    {
        const long long NC3 = (long long)NN_ * 3 * CC;
        dim3 grid(DD / 64, NN_ / 64, Bb * HH);
        gemm64<false><<<grid, 256>>>(out_attn, p_qkv + 2 * CC, p_ao,
                                     NN_, DD, NN_, NN_, 3 * CC, CC,
                                     (long long)HH * NN_ * NN_, (long long)NN_ * NN_,
                                     NC3, DD,
                                     (long long)NN_ * CC, DD, HH,
                                     nullptr, nullptr, 0);
    }

    // 6) proj + residual: g_x1 = x + g_attnout @ proj_w^T + proj_b
    {
        dim3 grid(CC / 64, M / 64, 1);
        gemm64<true><<<grid, 256>>>(p_ao, proj_w, p_x1,
                                    M, CC, CC, CC, CC, CC,
                                    ZERO, ZERO, ZERO, ZERO, ZERO, ZERO, 1,
                                    proj_b, x, 0);
    }

    // 7) LN2: g_ln = layernorm(g_x1)
    ln_kernel<<<M, 256>>>(p_x1, ln2_g, ln2_b, p_ln);

    // 8) FC1 + GELU: g_hbuf = gelu(g_ln @ fc1_w^T + fc1_b)
    {
        dim3 grid(DFF_ / 64, M / 64, 1);
        gemm64<true><<<grid, 256>>>(p_ln, fc1_w, p_h,
                                    M, DFF_, CC, CC, CC, DFF_,
                                    ZERO, ZERO, ZERO, ZERO, ZERO, ZERO, 1,
                                    fc1_b, nullptr, 1);
    }

    // 9) FC2 + residual: out_x = g_x1 + g_hbuf @ fc2_w^T + fc2_b
    {
        dim3 grid(CC / 64, M / 64, 1);
        gemm64<true><<<grid, 256>>>(p_h, fc2_w, out_x,
                                    M, CC, DFF_, DFF_, DFF_, CC,
                                    ZERO, ZERO, ZERO, ZERO, ZERO, ZERO, 1,
                                    fc2_b, p_x1, 0);
    }
}

// round 2
// speedup vs baseline: 2.9537x; 2.9537x over previous
#include <cuda_runtime.h>
#include <cuda_bf16.h>
#include <math.h>

// Problem constants
#define Bb   2
#define NN_  2048
#define CC   1024
#define HH   16
#define DD   64
#define DFF_ 4096

// Scratch buffers (static device globals — allocation-free rule)
__device__ float g_ln[Bb * NN_ * CC];
__device__ float g_qkv[Bb * NN_ * 3 * CC];
__device__ float g_attnout[Bb * NN_ * CC];
__device__ float g_x1[Bb * NN_ * CC];
__device__ float g_hbuf[Bb * NN_ * DFF_];

// ---------------------------------------------------------------------------
// LayerNorm: one block (256 threads) per row of C=1024
// ---------------------------------------------------------------------------
__global__ void ln_kernel(const float* __restrict__ x,
                          const float* __restrict__ g,
                          const float* __restrict__ b,
                          float* __restrict__ out)
{
    int row = blockIdx.x;
    long long base = (long long)row * CC;
    int t = threadIdx.x;

    float v[4];
    float s = 0.f, s2 = 0.f;
#pragma unroll
    for (int i = 0; i < 4; i++) {
        v[i] = x[base + t + i * 256];
        s  += v[i];
        s2 += v[i] * v[i];
    }
#pragma unroll
    for (int o = 16; o; o >>= 1) {
        s  += __shfl_xor_sync(0xffffffffu, s, o);
        s2 += __shfl_xor_sync(0xffffffffu, s2, o);
    }
    __shared__ float sh[16];
    int w = t >> 5, l = t & 31;
    if (l == 0) { sh[w] = s; sh[8 + w] = s2; }
    __syncthreads();
    if (t == 0) {
        float a = 0.f, c = 0.f;
#pragma unroll
        for (int i = 0; i < 8; i++) { a += sh[i]; c += sh[8 + i]; }
        sh[0] = a; sh[8] = c;
    }
    __syncthreads();
    float mu  = sh[0] * (1.0f / CC);
    float var = sh[8] * (1.0f / CC) - mu * mu;
    float inv = rsqrtf(var + 1e-5f);
#pragma unroll
    for (int i = 0; i < 4; i++) {
        int c = t + i * 256;
        out[base + c] = (v[i] - mu) * inv * g[c] + b[c];
    }
}

// ---------------------------------------------------------------------------
// TF32 tensor-core GEMM:  C = A @ op(B)  (+bias, +gelu, +residual)
//   BT=true : B is [Nc, K] row-major (dot of rows; torch Linear weight)
//   BT=false: B is [K, Nc] row-major
// Tile BM x BN, BK=32, 256 threads (8 warps: 4x2), warp tile (BM/4) x (BN/2).
// mma.sync.aligned.m16n8k8.row.col.f32.tf32.tf32.f32
// All dims must divide the tile sizes (true for this problem).
// ---------------------------------------------------------------------------
__device__ __forceinline__ float gelu_exact(float v) {
    return 0.5f * v * (1.0f + erff(v * 0.70710678118654752f));
}

__device__ __forceinline__ unsigned f2tf32(float f) {
    unsigned u;
    asm("cvt.rna.tf32.f32 %0, %1;" : "=r"(u) : "f"(f));
    return u;
}

__device__ __forceinline__ void mma_tf32(float* d, const unsigned* a, const unsigned* b) {
    asm volatile(
        "mma.sync.aligned.m16n8k8.row.col.f32.tf32.tf32.f32 "
        "{%0,%1,%2,%3}, {%4,%5,%6,%7}, {%8,%9}, {%0,%1,%2,%3};\n"
        : "+f"(d[0]), "+f"(d[1]), "+f"(d[2]), "+f"(d[3])
        : "r"(a[0]), "r"(a[1]), "r"(a[2]), "r"(a[3]),
          "r"(b[0]), "r"(b[1]));
}

template <bool BT, int BM, int BN>
__global__ __launch_bounds__(256)
void gemm_tc(const float* __restrict__ A, const float* __restrict__ Bm,
             float* __restrict__ Cc,
             int M, int Nc, int K, int lda, int ldb, int ldc,
             long long Abs, long long Ahs,
             long long Bbs, long long Bhs,
             long long Cbs, long long Chs, int Hh,
             const float* __restrict__ bias,
             const float* __restrict__ res, int act)
{
    constexpr int BK = 32;
    constexpr int WM = BM / 4;          // warp tile M (4 warps along M)
    constexpr int WN = BN / 2;          // warp tile N (2 warps along N)
    constexpr int MT = WM / 16;         // m16 tiles per warp
    constexpr int NT = WN / 8;          // n8 tiles per warp
    constexpr int LDS_ = BK + 4;        // 36: frag loads conflict-free

    __shared__ unsigned As[BM][LDS_];
    __shared__ unsigned Bs[BN][LDS_];

    int zb = blockIdx.z / Hh, zh = blockIdx.z % Hh;
    A  += zb * Abs + zh * Ahs;
    Bm += zb * Bbs + zh * Bhs;
    Cc += zb * Cbs + zh * Chs;

    int t = threadIdx.x;
    int w = t >> 5, lane = t & 31;
    int gid = lane >> 2, tig = lane & 3;
    int m0 = blockIdx.y * BM, n0 = blockIdx.x * BN;
    int wm = (w & 3) * WM, wn = (w >> 2) * WN;

    float acc[MT][NT][4] = {};

    // global-load indices
    int la_col = (t & 7) * 4;     // 0..28
    int la_row = t >> 3;          // 0..31
    int lb_nc  = (t & 15) * 4;    // for BT=false: 0..60
    int lb_kr  = t >> 4;          // 0..15

    for (int k0 = 0; k0 < K; k0 += BK) {
        // ---- load A tile (BM x BK, K-major) ----
#pragma unroll
        for (int r = la_row; r < BM; r += 32) {
            float4 v = *reinterpret_cast<const float4*>(
                &A[(long long)(m0 + r) * lda + k0 + la_col]);
            As[r][la_col + 0] = f2tf32(v.x);
            As[r][la_col + 1] = f2tf32(v.y);
            As[r][la_col + 2] = f2tf32(v.z);
            As[r][la_col + 3] = f2tf32(v.w);
        }
        // ---- load B tile into Bs[n][k] ----
        if (BT) {
#pragma unroll
            for (int r = la_row; r < BN; r += 32) {
                float4 v = *reinterpret_cast<const float4*>(
                    &Bm[(long long)(n0 + r) * ldb + k0 + la_col]);
                Bs[r][la_col + 0] = f2tf32(v.x);
                Bs[r][la_col + 1] = f2tf32(v.y);
                Bs[r][la_col + 2] = f2tf32(v.z);
                Bs[r][la_col + 3] = f2tf32(v.w);
            }
        } else {
            static_assert(BN <= 64 || BT, "non-BT path sized for BN<=64");
#pragma unroll
            for (int k2 = lb_kr; k2 < BK; k2 += 16) {
                float4 v = *reinterpret_cast<const float4*>(
                    &Bm[(long long)(k0 + k2) * ldb + n0 + lb_nc]);
                Bs[lb_nc + 0][k2] = f2tf32(v.x);
                Bs[lb_nc + 1][k2] = f2tf32(v.y);
                Bs[lb_nc + 2][k2] = f2tf32(v.z);
                Bs[lb_nc + 3][k2] = f2tf32(v.w);
            }
        }
        __syncthreads();

#pragma unroll
        for (int kk = 0; kk < BK; kk += 8) {
            unsigned af[MT][4], bf[NT][2];
#pragma unroll
            for (int i = 0; i < MT; i++) {
                int r = wm + i * 16 + gid;
                af[i][0] = As[r][kk + tig];
                af[i][1] = As[r + 8][kk + tig];
                af[i][2] = As[r][kk + tig + 4];
                af[i][3] = As[r + 8][kk + tig + 4];
            }
#pragma unroll
            for (int j = 0; j < NT; j++) {
                int c = wn + j * 8 + gid;
                bf[j][0] = Bs[c][kk + tig];
                bf[j][1] = Bs[c][kk + tig + 4];
            }
#pragma unroll
            for (int i = 0; i < MT; i++)
#pragma unroll
                for (int j = 0; j < NT; j++)
                    mma_tf32(acc[i][j], af[i], bf[j]);
        }
        __syncthreads();
    }

    // ---- epilogue ----
#pragma unroll
    for (int i = 0; i < MT; i++) {
        int r1 = m0 + wm + i * 16 + gid;
        int r2 = r1 + 8;
#pragma unroll
        for (int j = 0; j < NT; j++) {
            int c = n0 + wn + j * 8 + 2 * tig;
            float v0 = acc[i][j][0], v1 = acc[i][j][1];
            float v2 = acc[i][j][2], v3 = acc[i][j][3];
            if (bias) {
                float b0 = bias[c], b1 = bias[c + 1];
                v0 += b0; v1 += b1; v2 += b0; v3 += b1;
            }
            if (act) {
                v0 = gelu_exact(v0); v1 = gelu_exact(v1);
                v2 = gelu_exact(v2); v3 = gelu_exact(v3);
            }
            long long i1 = (long long)r1 * ldc + c;
            long long i2 = (long long)r2 * ldc + c;
            if (res) {
                float2 ra = *reinterpret_cast<const float2*>(&res[i1]);
                float2 rb = *reinterpret_cast<const float2*>(&res[i2]);
                v0 += ra.x; v1 += ra.y; v2 += rb.x; v3 += rb.y;
            }
            float2 o1 = {v0, v1}, o2 = {v2, v3};
            *reinterpret_cast<float2*>(&Cc[i1]) = o1;
            *reinterpret_cast<float2*>(&Cc[i2]) = o2;
        }
    }
}

// ---------------------------------------------------------------------------
// Softmax (in place on attn logits): applies scale + mask, row length N=2048.
// ---------------------------------------------------------------------------
__global__ void softmax_kernel(float* __restrict__ attn,
                               const int* __restrict__ mask)
{
    long long row = blockIdx.x;
    int bidx = (int)(row / ((long long)HH * NN_));
    float* r = attn + row * NN_;
    const int* mr = mask + (long long)bidx * NN_;
    int t = threadIdx.x;

    const float scale = 0.125f;

    float v[8];
    float mx = -INFINITY;
#pragma unroll
    for (int i = 0; i < 8; i++) {
        int c = t + i * 256;
        float val = mr[c] ? r[c] * scale : -INFINITY;
        v[i] = val;
        mx = fmaxf(mx, val);
    }
#pragma unroll
    for (int o = 16; o; o >>= 1)
        mx = fmaxf(mx, __shfl_xor_sync(0xffffffffu, mx, o));

    __shared__ float shm[8], shs[8];
    int w = t >> 5, l = t & 31;
    if (l == 0) shm[w] = mx;
    __syncthreads();
    float m2 = shm[0];
#pragma unroll
    for (int i = 1; i < 8; i++) m2 = fmaxf(m2, shm[i]);

    float se = 0.f;
#pragma unroll
    for (int i = 0; i < 8; i++) {
        v[i] = expf(v[i] - m2);
        se += v[i];
    }
#pragma unroll
    for (int o = 16; o; o >>= 1)
        se += __shfl_xor_sync(0xffffffffu, se, o);
    if (l == 0) shs[w] = se;
    __syncthreads();
    float tot = 0.f;
#pragma unroll
    for (int i = 0; i < 8; i++) tot += shs[i];
    float inv = 1.0f / tot;

#pragma unroll
    for (int i = 0; i < 8; i++) {
        int c = t + i * 256;
        r[c] = v[i] * inv;
    }
}

// ---------------------------------------------------------------------------
// Launch
// ---------------------------------------------------------------------------
extern "C" void kernel_launch(void* const* d_in, const int* in_sizes, int n_in,
                              void* d_out, int out_size)
{
    const float* x      = (const float*)d_in[0];
    const int*   mask   = (const int*)  d_in[1];
    const float* qkv_w  = (const float*)d_in[2];
    const float* proj_w = (const float*)d_in[3];
    const float* proj_b = (const float*)d_in[4];
    const float* ln1_g  = (const float*)d_in[5];
    const float* ln1_b  = (const float*)d_in[6];
    const float* ln2_g  = (const float*)d_in[7];
    const float* ln2_b  = (const float*)d_in[8];
    const float* fc1_w  = (const float*)d_in[9];
    const float* fc1_b  = (const float*)d_in[10];
    const float* fc2_w  = (const float*)d_in[11];
    const float* fc2_b  = (const float*)d_in[12];

    float* out_x    = (float*)d_out;
    float* out_attn = out_x + (long long)Bb * NN_ * CC;

    float *p_ln, *p_qkv, *p_ao, *p_x1, *p_h;
    cudaGetSymbolAddress((void**)&p_ln,  g_ln);
    cudaGetSymbolAddress((void**)&p_qkv, g_qkv);
    cudaGetSymbolAddress((void**)&p_ao,  g_attnout);
    cudaGetSymbolAddress((void**)&p_x1,  g_x1);
    cudaGetSymbolAddress((void**)&p_h,   g_hbuf);

    const int M  = Bb * NN_;                 // 4096
    const long long ZERO = 0;
    const long long NC3 = (long long)NN_ * 3 * CC;

    // 1) LN1
    ln_kernel<<<M, 256>>>(x, ln1_g, ln1_b, p_ln);

    // 2) QKV: [4096,3072] = ln @ qkv_w^T
    {
        dim3 grid(3 * CC / 128, M / 128, 1);
        gemm_tc<true, 128, 128><<<grid, 256>>>(p_ln, qkv_w, p_qkv,
            M, 3 * CC, CC, CC, CC, 3 * CC,
            ZERO, ZERO, ZERO, ZERO, ZERO, ZERO, 1,
            nullptr, nullptr, 0);
    }

    // 3) QK^T per head -> out_attn (raw logits)
    {
        dim3 grid(NN_ / 128, NN_ / 128, Bb * HH);
        gemm_tc<true, 128, 128><<<grid, 256>>>(p_qkv, p_qkv + CC, out_attn,
            NN_, NN_, DD, 3 * CC, 3 * CC, NN_,
            NC3, DD, NC3, DD,
            (long long)HH * NN_ * NN_, (long long)NN_ * NN_, HH,
            nullptr, nullptr, 0);
    }

    // 4) softmax (scale + mask), in place
    softmax_kernel<<<Bb * HH * NN_, 256>>>(out_attn, mask);

    // 5) AV per head: [2048,64] = attn @ V
    {
        dim3 grid(1, NN_ / 128, Bb * HH);
        gemm_tc<false, 128, 64><<<grid, 256>>>(out_attn, p_qkv + 2 * CC, p_ao,
            NN_, DD, NN_, NN_, 3 * CC, CC,
            (long long)HH * NN_ * NN_, (long long)NN_ * NN_,
            NC3, DD,
            (long long)NN_ * CC, DD, HH,
            nullptr, nullptr, 0);
    }

    // 6) proj + residual: x1 = x + ao @ proj_w^T + proj_b
    {
        dim3 grid(CC / 128, M / 128, 1);
        gemm_tc<true, 128, 128><<<grid, 256>>>(p_ao, proj_w, p_x1,
            M, CC, CC, CC, CC, CC,
            ZERO, ZERO, ZERO, ZERO, ZERO, ZERO, 1,
            proj_b, x, 0);
    }

    // 7) LN2
    ln_kernel<<<M, 256>>>(p_x1, ln2_g, ln2_b, p_ln);

    // 8) FC1 + GELU
    {
        dim3 grid(DFF_ / 128, M / 128, 1);
        gemm_tc<true, 128, 128><<<grid, 256>>>(p_ln, fc1_w, p_h,
            M, DFF_, CC, CC, CC, DFF_,
            ZERO, ZERO, ZERO, ZERO, ZERO, ZERO, 1,
            fc1_b, nullptr, 1);
    }

    // 9) FC2 + residual
    {
        dim3 grid(CC / 128, M / 128, 1);
        gemm_tc<true, 128, 128><<<grid, 256>>>(p_h, fc2_w, out_x,
            M, CC, DFF_, DFF_, DFF_, CC,
            ZERO, ZERO, ZERO, ZERO, ZERO, ZERO, 1,
            fc2_b, p_x1, 0);
    }
}